// round 8
// baseline (speedup 1.0000x reference)
#include <cuda_runtime.h>
#include <cuda_bf16.h>
#include <cstdint>

#define N_NODES  50000
#define N_REL    16
#define HID      128
#define N_LAYERS 3
#define N_EDGES  1600000
#define NSEG     (N_NODES * N_REL)   // 800000
#define NCHUNK   (N_REL + 1)         // 16 relations + root
#define W_ELEMS  (N_LAYERS * NCHUNK * 16384)

// ================= device scratch (no cudaMalloc allowed) =================
__device__ __align__(16) float g_bufA[(size_t)N_NODES * HID];
__device__ __align__(16) float g_bufB[(size_t)N_NODES * HID];
// weight stack: per layer 17 tiles of [n][k] bf16 (16 relations + root)
__device__ __align__(16) __nv_bfloat16 g_whi[(size_t)W_ELEMS];
__device__ __align__(16) __nv_bfloat16 g_wlo[(size_t)W_ELEMS];
__device__ int g_cnt[NSEG];
__device__ int g_segstart[NSEG];  // block-local exclusive scan (finalize with blkoff)
__device__ int g_cursor[NSEG];
__device__ int g_blksum[1024];
__device__ int g_blkoff[1024];
__device__ int g_eseg[N_EDGES];
__device__ int g_esrc[N_EDGES];
__device__ int g_srcSorted[N_EDGES];

// ================= helpers =================
__device__ __forceinline__ uint32_t smem_to_u32(const void* p) {
    uint32_t a;
    asm("{ .reg .u64 t; cvta.to.shared.u64 t, %1; cvt.u32.u64 %0, t; }"
        : "=r"(a) : "l"(p));
    return a;
}
__device__ __forceinline__ void ldsm_x4(uint32_t* r, uint32_t addr) {
    asm volatile("ldmatrix.sync.aligned.m8n8.x4.shared.b16 {%0,%1,%2,%3}, [%4];"
        : "=r"(r[0]), "=r"(r[1]), "=r"(r[2]), "=r"(r[3]) : "r"(addr));
}
__device__ __forceinline__ void mma_bf16(float* d, const uint32_t* a, const uint32_t* b) {
    asm volatile("mma.sync.aligned.m16n8k16.row.col.f32.bf16.bf16.f32 "
        "{%0,%1,%2,%3}, {%4,%5,%6,%7}, {%8,%9}, {%0,%1,%2,%3};"
        : "+f"(d[0]), "+f"(d[1]), "+f"(d[2]), "+f"(d[3])
        : "r"(a[0]), "r"(a[1]), "r"(a[2]), "r"(a[3]), "r"(b[0]), "r"(b[1]));
}
__device__ __forceinline__ void split_store(char* hi, char* lo, float a, float b) {
    __nv_bfloat16 h0 = __float2bfloat16(a), h1 = __float2bfloat16(b);
    __nv_bfloat16 l0 = __float2bfloat16(a - __bfloat162float(h0));
    __nv_bfloat16 l1 = __float2bfloat16(b - __bfloat162float(h1));
    *(__nv_bfloat162*)hi = __nv_bfloat162(h0, h1);
    *(__nv_bfloat162*)lo = __nv_bfloat162(l0, l1);
}

// ================= prep (5 launches total) =================================
// k1: zero counters + convert weights (fused)
__global__ void prep0_kernel(const float* __restrict__ W,
                             const float* __restrict__ root) {
    int t = blockIdx.x * blockDim.x + threadIdx.x;
    if (t < NSEG) { g_cnt[t] = 0; g_cursor[t] = 0; }
    if (t < W_ELEMS) {
        int tt  = t >> 14;
        int rem = t & 16383;
        int n = rem >> 7;
        int k = rem & 127;
        int l = tt / NCHUNK;
        int c = tt % NCHUNK;
        float v;
        if (c < N_REL) v = W[(((size_t)l * N_REL + c) * HID + k) * HID + n];
        else           v = root[((size_t)l * HID + k) * HID + n];
        __nv_bfloat16 hi = __float2bfloat16(v);
        __nv_bfloat16 lo = __float2bfloat16(v - __bfloat162float(hi));
        size_t off = (size_t)tt * 16384 + n * HID + k;
        g_whi[off] = hi;
        g_wlo[off] = lo;
    }
}
// k2: histogram + edge staging
__global__ void prep_edges_kernel(const int* __restrict__ edge_index,
                                  const int* __restrict__ edge_type) {
    int e = blockIdx.x * blockDim.x + threadIdx.x;
    if (e >= N_EDGES) return;
    int s = edge_index[e];
    int t = edge_index[N_EDGES + e];
    int r = edge_type[e];
    if ((unsigned)s >= N_NODES || (unsigned)t >= N_NODES || (unsigned)r >= N_REL) {
        g_eseg[e] = -1; g_esrc[e] = 0; return;
    }
    g_eseg[e] = t * N_REL + r;
    g_esrc[e] = s;
    atomicAdd(&g_cnt[t * N_REL + r], 1);
}
// k3: per-block exclusive scan of cnt
__global__ void scan1_kernel() {
    __shared__ int s[256];
    int base = blockIdx.x * 1024;
    int t = threadIdx.x;
    int v[4]; int sum = 0;
    #pragma unroll
    for (int j = 0; j < 4; j++) {
        int idx = base + t * 4 + j;
        v[j] = (idx < NSEG) ? g_cnt[idx] : 0;
        sum += v[j];
    }
    s[t] = sum; __syncthreads();
    for (int off = 1; off < 256; off <<= 1) {
        int x = 0;
        if (t >= off) x = s[t - off];
        __syncthreads();
        if (t >= off) s[t] += x;
        __syncthreads();
    }
    int excl = (t > 0) ? s[t - 1] : 0;
    if (t == 255) g_blksum[blockIdx.x] = s[255];
    int run = excl;
    #pragma unroll
    for (int j = 0; j < 4; j++) {
        int idx = base + t * 4 + j;
        if (idx < NSEG) g_segstart[idx] = run;
        run += v[j];
    }
}
// k4: scan of block sums
__global__ void scan2_kernel(int nb) {
    __shared__ int s[256];
    int t = threadIdx.x;
    int v[4]; int sum = 0;
    #pragma unroll
    for (int j = 0; j < 4; j++) {
        int idx = t * 4 + j;
        v[j] = (idx < nb) ? g_blksum[idx] : 0;
        sum += v[j];
    }
    s[t] = sum; __syncthreads();
    for (int off = 1; off < 256; off <<= 1) {
        int x = 0;
        if (t >= off) x = s[t - off];
        __syncthreads();
        if (t >= off) s[t] += x;
        __syncthreads();
    }
    int excl = (t > 0) ? s[t - 1] : 0;
    int run = excl;
    #pragma unroll
    for (int j = 0; j < 4; j++) {
        int idx = t * 4 + j;
        if (idx < nb) g_blkoff[idx] = run;
        run += v[j];
    }
}
// k5: counting-sort bin (segstart finalized on the fly via blkoff)
__global__ void bin_edges_kernel() {
    int e = blockIdx.x * blockDim.x + threadIdx.x;
    if (e >= N_EDGES) return;
    int seg = g_eseg[e];
    if (seg < 0) return;
    int base = g_segstart[seg] + g_blkoff[seg >> 10];
    int pos = base + atomicAdd(&g_cursor[seg], 1);
    g_srcSorted[pos] = g_esrc[e];
}

// ================= fused layer kernel ======================================
// out = [mean_agg(x) | x] @ [Wstk; root] + bias.  Aggregation is built
// per-chunk directly into the MMA smem A tile (no DRAM intermediate).
#define TPAD      136
#define TILE_B    (128 * TPAD * 2)           // 34816 bytes
#define SM_AHI    0
#define SM_ALO    (SM_AHI + TILE_B)
#define SM_BHI    (SM_ALO + TILE_B)
#define SM_BLO    (SM_BHI + TILE_B)
#define SM_META   (SM_BLO + TILE_B)          // s_start[2048], s_cnt[2048]
#define SM_TOTAL  (SM_META + 2048 * 8)       // 155648 bytes

__global__ __launch_bounds__(512) void rgcn_layer_fused(
    const float* __restrict__ xin,
    const __nv_bfloat16* __restrict__ whi,   // layer's 17-tile stack
    const __nv_bfloat16* __restrict__ wlo,
    const float* __restrict__ bias,
    float* __restrict__ out, int relu)
{
    extern __shared__ __align__(16) char smem[];
    const uint32_t sb = smem_to_u32(smem);
    int* s_start = (int*)(smem + SM_META);
    int* s_cnt   = (int*)(smem + SM_META + 2048 * 4);
    const int tid  = threadIdx.x;
    const int wid  = tid >> 5;
    const int lane = tid & 31;
    const int rowBase = blockIdx.x * 128;

    // ---- preload segment metadata for this CTA's 2048 (node,rel) segments --
    for (int i = tid; i < 2048; i += 512) {
        int kc = i >> 7, m = i & 127;
        int node = rowBase + m;
        int st = 0, c = 0;
        if (node < N_NODES) {
            int seg = node * N_REL + kc;
            st = g_segstart[seg] + g_blkoff[seg >> 10];
            c  = g_cnt[seg];
        }
        s_start[i] = st;
        s_cnt[i]   = c;
    }

    const int mW = (wid & 3) * 32;
    const int nW = (wid >> 2) * 32;

    float acc[2][4][4];
    #pragma unroll
    for (int mt = 0; mt < 2; mt++)
        #pragma unroll
        for (int nt = 0; nt < 4; nt++)
            #pragma unroll
            for (int q = 0; q < 4; q++) acc[mt][nt][q] = 0.0f;

    for (int kc = 0; kc < NCHUNK; kc++) {
        __syncthreads();   // prior chunk's ldsm reads + metadata ready
        // ---- build A chunk ----
        if (kc < N_REL) {
            // gather-mean: warp w handles rows w*8..w*8+7; lane covers 4 hid
            #pragma unroll
            for (int j = 0; j < 8; j++) {
                int m = wid * 8 + j;
                int meta = kc * 128 + m;
                int c  = s_cnt[meta];
                int st = s_start[meta];
                float4 sum = make_float4(0.f, 0.f, 0.f, 0.f);
                for (int i = 0; i < c; i++) {
                    int s = __ldg(g_srcSorted + st + i);
                    float4 v = __ldg((const float4*)(xin + (size_t)s * HID) + lane);
                    if (relu) { v.x = fmaxf(v.x,0.f); v.y = fmaxf(v.y,0.f);
                                v.z = fmaxf(v.z,0.f); v.w = fmaxf(v.w,0.f); }
                    sum.x += v.x; sum.y += v.y; sum.z += v.z; sum.w += v.w;
                }
                float inv = (c > 0) ? 1.0f / (float)c : 0.0f;
                sum.x *= inv; sum.y *= inv; sum.z *= inv; sum.w *= inv;
                // lane owns hid [lane*4, lane*4+4) -> byte offset lane*8 (bf16)
                uint32_t boff = (uint32_t)m * (TPAD * 2) + lane * 8;
                split_store(smem + SM_AHI + boff,     smem + SM_ALO + boff,     sum.x, sum.y);
                split_store(smem + SM_AHI + boff + 4, smem + SM_ALO + boff + 4, sum.z, sum.w);
            }
        } else {
            // root chunk: x + relu + split (8 float4/thread)
            #pragma unroll
            for (int i = 0; i < 8; i++) {
                int idx4 = tid + i * 512;        // 0..4095
                int row = idx4 >> 5, kq = (idx4 & 31) << 2;
                int gr = rowBase + row;
                float4 v = make_float4(0.f,0.f,0.f,0.f);
                if (gr < N_NODES) v = *(const float4*)(xin + (size_t)gr * HID + kq);
                if (relu) { v.x = fmaxf(v.x,0.f); v.y = fmaxf(v.y,0.f);
                            v.z = fmaxf(v.z,0.f); v.w = fmaxf(v.w,0.f); }
                uint32_t boff = (uint32_t)row * (TPAD * 2) + kq * 2;
                split_store(smem + SM_AHI + boff,     smem + SM_ALO + boff,     v.x, v.y);
                split_store(smem + SM_AHI + boff + 4, smem + SM_ALO + boff + 4, v.z, v.w);
            }
        }
        // ---- B chunk (L2-resident weight stack), 4 float4/thread ----
        {
            const __nv_bfloat16* bh = whi + (size_t)kc * 16384;
            const __nv_bfloat16* bl = wlo + (size_t)kc * 16384;
            #pragma unroll
            for (int i = 0; i < 4; i++) {
                int idx4 = tid + i * 512;        // 0..2047
                int row = idx4 >> 4, c16 = idx4 & 15;
                *(float4*)(smem + SM_BHI + row * (TPAD*2) + c16 * 16) =
                    *(const float4*)(bh + row * HID + c16 * 8);
                *(float4*)(smem + SM_BLO + row * (TPAD*2) + c16 * 16) =
                    *(const float4*)(bl + row * HID + c16 * 8);
            }
        }
        __syncthreads();

        // ---- MMA: 3 split terms over this 128-K chunk ----
        #pragma unroll
        for (int term = 0; term < 3; term++) {
            const uint32_t aBase = sb + (term == 2 ? SM_ALO : SM_AHI);
            const uint32_t bBase = sb + (term == 1 ? SM_BLO : SM_BHI);
            #pragma unroll
            for (int k0 = 0; k0 < HID; k0 += 16) {
                uint32_t a[2][4];
                {
                    int ar = mW + (lane & 15);
                    int ac = k0 + ((lane >> 4) << 3);
                    ldsm_x4(a[0], aBase + (uint32_t)ar * (TPAD*2) + ac * 2);
                    ldsm_x4(a[1], aBase + (uint32_t)(ar + 16) * (TPAD*2) + ac * 2);
                }
                uint32_t b[4][2];
                #pragma unroll
                for (int p = 0; p < 2; p++) {
                    int g  = lane >> 3;
                    int nn = nW + p * 16 + (lane & 7) + ((g >> 1) << 3);
                    int kk = k0 + ((g & 1) << 3);
                    uint32_t r[4];
                    ldsm_x4(r, bBase + (uint32_t)nn * (TPAD*2) + kk * 2);
                    b[p*2][0] = r[0]; b[p*2][1] = r[1];
                    b[p*2+1][0] = r[2]; b[p*2+1][1] = r[3];
                }
                #pragma unroll
                for (int mt = 0; mt < 2; mt++)
                    #pragma unroll
                    for (int nt = 0; nt < 4; nt++)
                        mma_bf16(acc[mt][nt], a[mt], b[nt]);
            }
        }
    }

    // ---- epilogue: + bias, direct store ----
    #pragma unroll
    for (int mt = 0; mt < 2; mt++) {
        int r0 = rowBase + mW + mt * 16 + (lane >> 2);
        int r1 = r0 + 8;
        #pragma unroll
        for (int nt = 0; nt < 4; nt++) {
            int col = nW + nt * 8 + (lane & 3) * 2;
            float b0 = bias[col], b1 = bias[col + 1];
            if (r0 < N_NODES)
                *(float2*)(out + (size_t)r0 * HID + col) =
                    make_float2(acc[mt][nt][0] + b0, acc[mt][nt][1] + b1);
            if (r1 < N_NODES)
                *(float2*)(out + (size_t)r1 * HID + col) =
                    make_float2(acc[mt][nt][2] + b0, acc[mt][nt][3] + b1);
        }
    }
}

// ================= launch ================================================
extern "C" void kernel_launch(void* const* d_in, const int* in_sizes, int n_in,
                              void* d_out, int out_size)
{
    const int*   edge_index = (const int*)d_in[0];
    const int*   edge_type  = (const int*)d_in[1];
    const float* node_init  = (const float*)d_in[2];
    const float* W          = (const float*)d_in[3];
    const float* root       = (const float*)d_in[4];
    const float* bias       = (const float*)d_in[5];
    float*       out        = (float*)d_out;

    void* p;
    cudaGetSymbolAddress(&p, g_bufA); float* bufA = (float*)p;
    cudaGetSymbolAddress(&p, g_bufB); float* bufB = (float*)p;
    cudaGetSymbolAddress(&p, g_whi);  __nv_bfloat16* whi = (__nv_bfloat16*)p;
    cudaGetSymbolAddress(&p, g_wlo);  __nv_bfloat16* wlo = (__nv_bfloat16*)p;

    cudaFuncSetAttribute(rgcn_layer_fused,
                         cudaFuncAttributeMaxDynamicSharedMemorySize, SM_TOTAL);

    const int scanBlocks = (NSEG + 1023) / 1024;   // 782
    prep0_kernel<<<(W_ELEMS + 255) / 256, 256>>>(W, root);
    prep_edges_kernel<<<(N_EDGES + 255) / 256, 256>>>(edge_index, edge_type);
    scan1_kernel<<<scanBlocks, 256>>>();
    scan2_kernel<<<1, 256>>>(scanBlocks);
    bin_edges_kernel<<<(N_EDGES + 255) / 256, 256>>>();

    const int rowTiles = (N_NODES + 127) / 128;    // 391
    const float* xin = node_init;

    for (int l = 0; l < N_LAYERS; l++) {
        float* xout = (l == N_LAYERS - 1) ? out : (l == 0 ? bufA : bufB);
        int relu = (l > 0) ? 1 : 0;
        rgcn_layer_fused<<<rowTiles, 512, SM_TOTAL>>>(
            xin, whi + (size_t)l * NCHUNK * 16384, wlo + (size_t)l * NCHUNK * 16384,
            bias + (size_t)l * HID, xout, relu);
        xin = xout;
    }
}